// round 7
// baseline (speedup 1.0000x reference)
#include <cuda_runtime.h>
#include <math.h>

#define D        1024
#define PD       32
#define NPAT     256
#define TOPK     4
#define NTOK_MAX 2048
#define CAP      2048          // worst case: every token picks this pattern
#define TB       32            // tokens per expert tile
#define ETHREADS 512
#define NTILE_CTAS 8           // CTAs per pattern (tile-parallel)
#define RTOKS    8             // tokens per route CTA

// ---------------- scratch (__device__ globals: allocation-free) ----------------
__device__ int   g_counts[NPAT];
__device__ int   g_lists[NPAT * CAP];                       // entry = tok*4 + k
__device__ float g_wts[NTOK_MAX * TOPK];                    // softmax weight * scale
__device__ float g_part[(size_t)NTOK_MAX * TOPK * D];       // 32 MB partials

// ---------------- kernel 0: zero counts ----------------
__global__ void zero_counts_kernel() { g_counts[threadIdx.x] = 0; }

// ---------------- kernel 1: routing (hash -> sim -> top4 -> softmax -> append) ----------------
__global__ __launch_bounds__(256) void route_kernel(
    const float* __restrict__ x,
    const float* __restrict__ hw,     // [PD, D]
    const float* __restrict__ keys,   // [NPAT, PD]
    const float* __restrict__ scale)
{
    __shared__ float xs[RTOKS * D];         // 32 KB
    __shared__ float h[RTOKS][PD];
    __shared__ float sims[RTOKS][NPAT];     // 8 KB
    __shared__ float sc_s;

    const int tid  = threadIdx.x;
    const int lane = tid & 31;
    const int w    = tid >> 5;
    const int tok0 = blockIdx.x * RTOKS;

    const float4* xg4 = reinterpret_cast<const float4*>(x) + (size_t)tok0 * (D / 4);
    float4* xs4 = reinterpret_cast<float4*>(xs);
    #pragma unroll
    for (int i = 0; i < RTOKS; i++) xs4[i * 256 + tid] = xg4[i * 256 + tid];
    if (tid == 0) sc_s = scale[0];
    __syncthreads();

    // hash: warp w computes h[t][j] for j = 4w..4w+3, all 8 tokens
    {
        const float4* hw4 = reinterpret_cast<const float4*>(hw);
        #pragma unroll
        for (int jj = 0; jj < 4; jj++) {
            const int j = w * 4 + jj;
            float acc[RTOKS];
            #pragma unroll
            for (int t = 0; t < RTOKS; t++) acc[t] = 0.f;
            #pragma unroll
            for (int i = 0; i < 8; i++) {
                const float4 hv = hw4[j * (D / 4) + lane + 32 * i];
                #pragma unroll
                for (int t = 0; t < RTOKS; t++) {
                    const float4 xv = xs4[t * 256 + lane + 32 * i];
                    acc[t] += hv.x * xv.x + hv.y * xv.y + hv.z * xv.z + hv.w * xv.w;
                }
            }
            #pragma unroll
            for (int t = 0; t < RTOKS; t++) {
                float a = acc[t];
                #pragma unroll
                for (int off = 16; off; off >>= 1)
                    a += __shfl_xor_sync(0xFFFFFFFFu, a, off);
                if (lane == 0) h[t][j] = a;
            }
        }
    }
    __syncthreads();

    // sims: thread = pattern
    {
        float kreg[PD];
        const float4* k4 = reinterpret_cast<const float4*>(keys) + tid * (PD / 4);
        #pragma unroll
        for (int i = 0; i < PD / 4; i++) {
            const float4 v = k4[i];
            kreg[4 * i] = v.x; kreg[4 * i + 1] = v.y;
            kreg[4 * i + 2] = v.z; kreg[4 * i + 3] = v.w;
        }
        #pragma unroll
        for (int t = 0; t < RTOKS; t++) {
            float s = 0.f;
            #pragma unroll
            for (int i = 0; i < PD; i++) s += kreg[i] * h[t][i];
            sims[t][tid] = s;
        }
    }
    __syncthreads();

    // top-4 + softmax per token (warp w owns token w); ties -> lower index
    {
        float kval[TOPK]; int kidx[TOPK];
        for (int k = 0; k < TOPK; k++) {
            float bv = -1e30f; int bi = 0;
            #pragma unroll
            for (int t2 = 0; t2 < 8; t2++) {
                const int n = lane * 8 + t2;
                const float v = sims[w][n];
                if (v > bv) { bv = v; bi = n; }
            }
            #pragma unroll
            for (int off = 16; off; off >>= 1) {
                const float ov = __shfl_xor_sync(0xFFFFFFFFu, bv, off);
                const int   oi = __shfl_xor_sync(0xFFFFFFFFu, bi, off);
                if (ov > bv || (ov == bv && oi < bi)) { bv = ov; bi = oi; }
            }
            if (lane == 0) { kval[k] = bv; kidx[k] = bi; sims[w][bi] = -1e30f; }
            __syncwarp();
        }
        if (lane == 0) {
            const int gtok = tok0 + w;
            const float m = kval[0];
            float e[TOPK]; float ssum = 0.f;
            #pragma unroll
            for (int k = 0; k < TOPK; k++) { e[k] = expf(kval[k] - m); ssum += e[k]; }
            const float sc = sc_s / ssum;
            #pragma unroll
            for (int k = 0; k < TOPK; k++) {
                const int p = kidx[k];
                const int entry = gtok * TOPK + k;
                g_wts[entry] = e[k] * sc;
                const int slot = atomicAdd(&g_counts[p], 1);
                g_lists[p * CAP + slot] = entry;
            }
        }
    }
}

// ---------------- kernel 2: per-pattern-tile expert (down -> silu -> up) ----------------
// grid = (NPAT, NTILE_CTAS). CTA (p, ti) handles tiles ti, ti+8, ...
// Down mapping: warp w -> (tg = w&3: 8 tokens, jg = w>>2: 8 j's)
//               lane    -> (tl = lane&7: token, jl = lane>>3: j-pair)
// Each thread owns one (token, j-pair), sums full K. No cross-warp reduction.
__global__ __launch_bounds__(ETHREADS, 1) void expert_kernel(
    const float* __restrict__ x,
    const float* __restrict__ vd,     // [NPAT, D, PD]
    const float* __restrict__ vu)     // [NPAT, PD, D]
{
    __shared__ float vds[128 * PD];   // 16 KB: one 128-row chunk of vd
    __shared__ float proj[TB * PD];   // 4 KB
    __shared__ float wts[TB];
    __shared__ int   ents[TB];
    __shared__ int   n_s;

    const int p   = blockIdx.x;
    const int tid = threadIdx.x;
    if (tid == 0) n_s = g_counts[p];
    __syncthreads();
    const int n = n_s;
    if ((int)blockIdx.y * TB >= n) return;

    const float4* vdg4 = reinterpret_cast<const float4*>(vd + (size_t)p * D * PD);
    const float2* vds2 = reinterpret_cast<const float2*>(vds);
    const float2* vug2 = reinterpret_cast<const float2*>(vu + (size_t)p * PD * D);
    const float4* xg4  = reinterpret_cast<const float4*>(x);
    const float4* pj4  = reinterpret_cast<const float4*>(proj);

    const int lane = tid & 31;
    const int w    = tid >> 5;
    const int tg   = w & 3;            // token group (8 tokens)
    const int jg   = w >> 2;           // j group (8 j's)
    const int tl   = lane & 7;
    const int jl   = lane >> 3;        // j-pair within group
    const int t    = tg * 8 + tl;      // token slot 0..31
    const int jcol = jg * 4 + jl;      // float2 column 0..15 (j = 2*jcol)

    for (int base = blockIdx.y * TB; base < n; base += NTILE_CTAS * TB) {
        const int nt = min(TB, n - base);

        if (tid < TB) {
            const int slot = (tid < nt) ? tid : 0;
            const int e = g_lists[p * CAP + base + slot];
            ents[tid] = e;
            wts[tid]  = (tid < nt) ? g_wts[e] : 0.f;
        }
        __syncthreads();

        // ---- down: proj[t][j] = sum_d x[t][d] * vd[d][j]
        const int myTok = ents[t] >> 2;               // padded slots -> slot0 (wt=0)
        const float4* xrow4 = xg4 + (size_t)myTok * 256;
        float accx = 0.f, accy = 0.f;

        float4* vds4 = reinterpret_cast<float4*>(vds);
        for (int dc = 0; dc < 8; dc++) {
            vds4[tid]       = vdg4[dc * 1024 + tid];
            vds4[tid + 512] = vdg4[dc * 1024 + tid + 512];
            __syncthreads();
            const float4* xq4 = xrow4 + dc * 32;
            #pragma unroll 8
            for (int q = 0; q < 32; q++) {
                const float4 xq = xq4[q];             // L1 broadcast across jl/jg
                float2 v0 = vds2[(4 * q + 0) * 16 + jcol];
                float2 v1 = vds2[(4 * q + 1) * 16 + jcol];
                float2 v2 = vds2[(4 * q + 2) * 16 + jcol];
                float2 v3 = vds2[(4 * q + 3) * 16 + jcol];
                accx += xq.x * v0.x + xq.y * v1.x + xq.z * v2.x + xq.w * v3.x;
                accy += xq.x * v0.y + xq.y * v1.y + xq.z * v2.y + xq.w * v3.y;
            }
            __syncthreads();
        }

        // silu * (softmax weight * scale)
        {
            const float wt = wts[t];
            proj[t * PD + 2 * jcol]     = accx / (1.f + expf(-accx)) * wt;
            proj[t * PD + 2 * jcol + 1] = accy / (1.f + expf(-accy)) * wt;
        }
        __syncthreads();

        // ---- up: part[t][d] = sum_j proj[t][j] * vu[j][d]
        // thread owns float2 of d; two 16-token halves (acc = 32 regs)
        #pragma unroll
        for (int h = 0; h < 2; h++) {
            float2 acc[16];
            #pragma unroll
            for (int tt = 0; tt < 16; tt++) acc[tt] = make_float2(0.f, 0.f);
            #pragma unroll
            for (int jq = 0; jq < 8; jq++) {
                float2 v0 = vug2[(4 * jq + 0) * 512 + tid];
                float2 v1 = vug2[(4 * jq + 1) * 512 + tid];
                float2 v2 = vug2[(4 * jq + 2) * 512 + tid];
                float2 v3 = vug2[(4 * jq + 3) * 512 + tid];
                #pragma unroll
                for (int tt = 0; tt < 16; tt++) {
                    const float4 pq = pj4[(h * 16 + tt) * 8 + jq];  // broadcast
                    acc[tt].x += pq.x * v0.x + pq.y * v1.x + pq.z * v2.x + pq.w * v3.x;
                    acc[tt].y += pq.x * v0.y + pq.y * v1.y + pq.z * v2.y + pq.w * v3.y;
                }
            }
            #pragma unroll
            for (int tt = 0; tt < 16; tt++) {
                const int slot = h * 16 + tt;
                if (slot < nt) {
                    float2* pp = reinterpret_cast<float2*>(g_part + (size_t)ents[slot] * D);
                    pp[tid] = acc[tt];
                }
            }
        }
        __syncthreads();   // protect ents/wts/proj before next tile
    }
}

// ---------------- kernel 3: gather out = x + sum_k partial ----------------
__global__ __launch_bounds__(256) void gather_kernel(
    const float* __restrict__ x, float* __restrict__ out)
{
    const int tok = blockIdx.x, tid = threadIdx.x;
    const float4* xg4 = reinterpret_cast<const float4*>(x) + (size_t)tok * 256;
    float4 o = xg4[tid];
    const float4* p4 = reinterpret_cast<const float4*>(g_part) + (size_t)tok * TOPK * 256;
    #pragma unroll
    for (int k = 0; k < TOPK; k++) {
        const float4 v = p4[k * 256 + tid];
        o.x += v.x; o.y += v.y; o.z += v.z; o.w += v.w;
    }
    reinterpret_cast<float4*>(out)[(size_t)tok * 256 + tid] = o;
}

// ---------------- launcher ----------------
extern "C" void kernel_launch(void* const* d_in, const int* in_sizes, int n_in,
                              void* d_out, int out_size) {
    const float* x     = (const float*)d_in[0];
    const float* hw    = (const float*)d_in[1];
    const float* keys  = (const float*)d_in[2];
    const float* vd    = (const float*)d_in[3];
    const float* vu    = (const float*)d_in[4];
    const float* scale = (const float*)d_in[5];
    float* out = (float*)d_out;

    const int ntok = in_sizes[0] / D;   // 2048

    zero_counts_kernel<<<1, NPAT>>>();
    route_kernel<<<ntok / RTOKS, 256>>>(x, hw, keys, scale);
    expert_kernel<<<dim3(NPAT, NTILE_CTAS), ETHREADS>>>(x, vd, vu);
    gather_kernel<<<ntok, 256>>>(x, out);
}